// round 11
// baseline (speedup 1.0000x reference)
#include <cuda_runtime.h>
#include <cstdint>
#include <cstddef>

#define LOG2E_F 1.4426950408889634f
#define LN2_F   0.6931471805599453f

__device__ __forceinline__ float ex2f_(float x) {
    float y; asm("ex2.approx.ftz.f32 %0, %1;" : "=f"(y) : "f"(x)); return y;
}
__device__ __forceinline__ float lg2f_(float x) {
    float y; asm("lg2.approx.f32 %0, %1;" : "=f"(y) : "f"(x)); return y;
}
__device__ __forceinline__ unsigned long long pk2(float lo, float hi) {
    unsigned long long r; asm("mov.b64 %0, {%1, %2};" : "=l"(r) : "f"(lo), "f"(hi)); return r;
}
__device__ __forceinline__ void upk2(unsigned long long v, float& lo, float& hi) {
    asm("mov.b64 {%0, %1}, %2;" : "=f"(lo), "=f"(hi) : "l"(v));
}
__device__ __forceinline__ void fma2_(unsigned long long& acc, unsigned long long a, unsigned long long b) {
    asm("fma.rn.f32x2 %0, %1, %2, %0;" : "+l"(acc) : "l"(a), "l"(b));
}
__device__ __forceinline__ unsigned long long add2_(unsigned long long a, unsigned long long b) {
    unsigned long long r; asm("add.rn.f32x2 %0, %1, %2;" : "=l"(r) : "l"(a), "l"(b)); return r;
}

// TWO batches per CTA fused in the SAME 8 warps (within-warp ILP).
// Exact R3 per-batch structure (the measured optimum: cp = tid>>2 -> column
// pair, ich = tid&3 -> 32-wide from-chunk; 16 LDS.64 + 32 fma2 + 2 shfl per
// batch; REDUX renorm every 8 steps; double-buffered padded smem), but each
// loop iteration advances BOTH batch b0=2*bid and b1=2*bid+1: their
// independent dependency chains are interleaved instruction-by-instruction
// in the matvec (guaranteed overlap, unlike the failed cross-warp attempts
// R7/R9), and ONE __syncthreads covers both batch-steps. The transition
// matrix registers A0/A1 are shared between the batches, so the marginal
// register cost is only v-loads/accumulators/obs-ring (~35 regs).
__global__ __launch_bounds__(256, 1)
void crf_fwd_kernel(const float* __restrict__ obs,
                    const float* __restrict__ logA,
                    float* __restrict__ out,
                    int T, int B)
{
    constexpr int S  = 128;
    constexpr int CH = 34;     // chunk stride (floats): 8B-aligned, bank-skewed
    __shared__ __align__(16) float v_a[2][4 * CH];
    __shared__ __align__(16) float v_b[2][4 * CH];
    __shared__ float wma[8], wmb[8];
    __shared__ float wsum[8];

    const int tid  = threadIdx.x;
    const int cp   = tid >> 2;
    const int ich  = tid & 3;
    const int j0   = cp * 2;
    const int warp = tid >> 5;
    const int wslot = ((j0 >> 5) * CH) + (j0 & 31);

    const int b0 = 2 * (int)blockIdx.x;
    const int b1 = (b0 + 1 < B) ? (b0 + 1) : b0;

    const float* oba = obs + (size_t)b0 * (size_t)T * S + j0;
    const float* obb = obs + (size_t)b1 * (size_t)T * S + j0;

    // Shared transition slice: A0[k] = {E[i0+2k][j0], E[i0+2k+1][j0]}, etc.
    unsigned long long A0[16], A1[16];
#pragma unroll
    for (int k = 0; k < 16; ++k) {
        const int i0 = ich * 32 + 2 * k;
        const float2 ea = *reinterpret_cast<const float2*>(logA + (size_t)i0 * S + j0);
        const float2 eb = *reinterpret_cast<const float2*>(logA + (size_t)(i0 + 1) * S + j0);
        A0[k] = pk2(ex2f_(ea.x * LOG2E_F), ex2f_(eb.x * LOG2E_F));
        A1[k] = pk2(ex2f_(ea.y * LOG2E_F), ex2f_(eb.y * LOG2E_F));
    }

    // ---- t = 0 (t%8==0): u = exp(obs[0]) raw; publish per-batch max ----
    const float2 o0a = *reinterpret_cast<const float2*>(oba);
    const float2 o0b = *reinterpret_cast<const float2*>(obb);
    const float ua0 = ex2f_(o0a.x * LOG2E_F), ua1 = ex2f_(o0a.y * LOG2E_F);
    const float ub0 = ex2f_(o0b.x * LOG2E_F), ub1 = ex2f_(o0b.y * LOG2E_F);
    {
        const int ia = __reduce_max_sync(0xffffffffu, __float_as_int(fmaxf(ua0, ua1)));
        const int ib = __reduce_max_sync(0xffffffffu, __float_as_int(fmaxf(ub0, ub1)));
        if ((tid & 31) == 0) { wma[warp] = __int_as_float(ia); wmb[warp] = __int_as_float(ib); }
        if (ich == 0) {
            float2 wa; wa.x = ua0; wa.y = ua1;
            float2 wb; wb.x = ub0; wb.y = ub1;
            *reinterpret_cast<float2*>(&v_a[0][wslot]) = wa;
            *reinterpret_cast<float2*>(&v_b[0][wslot]) = wb;
        }
    }

    // 4-deep obs prefetch rings.
    float2 oRa[4], oRb[4];
#pragma unroll
    for (int k = 1; k <= 4; ++k) {
        oRa[k & 3] = (k < T) ? __ldcs(reinterpret_cast<const float2*>(oba + (size_t)k * S)) : o0a;
        oRb[k & 3] = (k < T) ? __ldcs(reinterpret_cast<const float2*>(obb + (size_t)k * S)) : o0b;
    }

    int La = 0, Lb = 0;        // exact accumulated log2 scales
    __syncthreads();

    // ---- scan t = 1 .. T-1: both batches per iteration, ONE barrier ----
#pragma unroll 2
    for (int t = 1; t < T; ++t) {
        const int cb = (t - 1) & 1, nb = t & 1;

        const float2 oca = oRa[t & 3];
        const float2 ocb = oRb[t & 3];
        if (t + 4 < T) {
            oRa[t & 3] = __ldcs(reinterpret_cast<const float2*>(oba + (size_t)(t + 4) * S));
            oRb[t & 3] = __ldcs(reinterpret_cast<const float2*>(obb + (size_t)(t + 4) * S));
        }

        const float pa0 = ex2f_(oca.x * LOG2E_F), pa1 = ex2f_(oca.y * LOG2E_F);
        const float pb0 = ex2f_(ocb.x * LOG2E_F), pb1 = ex2f_(ocb.y * LOG2E_F);

        // fold previous publishes' exact 2^-e every 8th step
        float sca = 1.0f, scb = 1.0f;
        const bool fold = (t & 7) == 1;
        if (fold) {
            const float ma = fmaxf(fmaxf(fmaxf(wma[0], wma[1]), fmaxf(wma[2], wma[3])),
                                   fmaxf(fmaxf(wma[4], wma[5]), fmaxf(wma[6], wma[7])));
            const float mb = fmaxf(fmaxf(fmaxf(wmb[0], wmb[1]), fmaxf(wmb[2], wmb[3])),
                                   fmaxf(fmaxf(wmb[4], wmb[5]), fmaxf(wmb[6], wmb[7])));
            const int ea = ((__float_as_int(ma) >> 23) & 0xFF) - 127;
            const int eb = ((__float_as_int(mb) >> 23) & 0xFF) - 127;
            La += ea; Lb += eb;
            sca = __int_as_float((127 - ea) << 23);
            scb = __int_as_float((127 - eb) << 23);
        }

        // dual matvec, chains interleaved: 32 LDS.64 + 64 fma2 per thread
        const unsigned long long* Va =
            reinterpret_cast<const unsigned long long*>(&v_a[cb][ich * CH]);
        const unsigned long long* Vb =
            reinterpret_cast<const unsigned long long*>(&v_b[cb][ich * CH]);
        unsigned long long aA0 = 0ull, aB0 = 0ull, aA1 = 0ull, aB1 = 0ull;   // batch A
        unsigned long long bA0 = 0ull, bB0 = 0ull, bA1 = 0ull, bB1 = 0ull;   // batch B
#pragma unroll
        for (int k = 0; k < 8; ++k) {
            const unsigned long long va0 = Va[2 * k], va1 = Va[2 * k + 1];
            const unsigned long long vb0 = Vb[2 * k], vb1 = Vb[2 * k + 1];
            fma2_(aA0, va0, A0[2 * k]);
            fma2_(bA0, vb0, A0[2 * k]);
            fma2_(aA1, va0, A1[2 * k]);
            fma2_(bA1, vb0, A1[2 * k]);
            fma2_(aB0, va1, A0[2 * k + 1]);
            fma2_(bB0, vb1, A0[2 * k + 1]);
            fma2_(aB1, va1, A1[2 * k + 1]);
            fma2_(bB1, vb1, A1[2 * k + 1]);
        }
        float ax0, ay0, ax1, ay1, bx0, by0, bx1, by1;
        upk2(add2_(aA0, aB0), ax0, ay0);
        upk2(add2_(bA0, bB0), bx0, by0);
        upk2(add2_(aA1, aB1), ax1, ay1);
        upk2(add2_(bA1, bB1), bx1, by1);
        float accA0 = ax0 + ay0, accA1 = ax1 + ay1;
        float accB0 = bx0 + by0, accB1 = bx1 + by1;
        // butterflies, A/B interleaved so the two serial chains overlap
        accA0 += __shfl_xor_sync(0xffffffffu, accA0, 1);
        accB0 += __shfl_xor_sync(0xffffffffu, accB0, 1);
        accA1 += __shfl_xor_sync(0xffffffffu, accA1, 1);
        accB1 += __shfl_xor_sync(0xffffffffu, accB1, 1);
        accA0 += __shfl_xor_sync(0xffffffffu, accA0, 2);
        accB0 += __shfl_xor_sync(0xffffffffu, accB0, 2);
        accA1 += __shfl_xor_sync(0xffffffffu, accA1, 2);
        accB1 += __shfl_xor_sync(0xffffffffu, accB1, 2);

        const float unA0 = fold ? accA0 * (pa0 * sca) : accA0 * pa0;
        const float unA1 = fold ? accA1 * (pa1 * sca) : accA1 * pa1;
        const float unB0 = fold ? accB0 * (pb0 * scb) : accB0 * pb0;
        const float unB1 = fold ? accB1 * (pb1 * scb) : accB1 * pb1;

        if (ich == 0) {
            float2 wa; wa.x = unA0; wa.y = unA1;
            float2 wb; wb.x = unB0; wb.y = unB1;
            *reinterpret_cast<float2*>(&v_a[nb][wslot]) = wa;
            *reinterpret_cast<float2*>(&v_b[nb][wslot]) = wb;
        }
        // publish per-batch block max every 8th step (consumed at t+1)
        if ((t & 7) == 0) {
            const int ia = __reduce_max_sync(0xffffffffu, __float_as_int(fmaxf(unA0, unA1)));
            const int ib = __reduce_max_sync(0xffffffffu, __float_as_int(fmaxf(unB0, unB1)));
            if ((tid & 31) == 0) { wma[warp] = __int_as_float(ia); wmb[warp] = __int_as_float(ib); }
        }
        __syncthreads();
    }

    // ---- finalize both batches ----
    const int fb = (T - 1) & 1;
    float va = 0.f, vb = 0.f;
    if (tid < 128) {
        const int rs = ((tid >> 5) * CH) + (tid & 31);
        va = v_a[fb][rs];
        vb = v_b[fb][rs];
    }
#pragma unroll
    for (int o = 16; o; o >>= 1) {
        va += __shfl_xor_sync(0xffffffffu, va, o);
        vb += __shfl_xor_sync(0xffffffffu, vb, o);
    }
    if (tid < 128 && (tid & 31) == 0) {
        wsum[tid >> 5]     = va;
        wsum[4 + (tid >> 5)] = vb;
    }
    __syncthreads();
    if (tid == 0) {
        const float sa = (wsum[0] + wsum[1]) + (wsum[2] + wsum[3]);
        const float sb = (wsum[4] + wsum[5]) + (wsum[6] + wsum[7]);
        out[b0] = -LN2_F * (lg2f_(sa) + (float)La);
        out[b1] = -LN2_F * (lg2f_(sb) + (float)Lb);
    }
}

extern "C" void kernel_launch(void* const* d_in, const int* in_sizes, int n_in,
                              void* d_out, int out_size)
{
    const float* obs  = (const float*)d_in[0];   // [B, T, S] f32
    const float* logA = (const float*)d_in[1];   // [S, S]   f32
    float* out = (float*)d_out;                  // [B]      f32

    const int B = out_size;
    const int S = 128;
    const int T = in_sizes[0] / (B * S);

    const int grid = (B + 1) / 2;
    crf_fwd_kernel<<<grid, 256>>>(obs, logA, out, T, B);
}

// round 12
// speedup vs baseline: 1.1159x; 1.1159x over previous
#include <cuda_runtime.h>
#include <cstdint>
#include <cstddef>

#define LOG2E_F 1.4426950408889634f
#define LN2_F   0.6931471805599453f

__device__ __forceinline__ float ex2f_(float x) {
    float y; asm("ex2.approx.ftz.f32 %0, %1;" : "=f"(y) : "f"(x)); return y;
}
__device__ __forceinline__ float lg2f_(float x) {
    float y; asm("lg2.approx.f32 %0, %1;" : "=f"(y) : "f"(x)); return y;
}
__device__ __forceinline__ unsigned long long pk2(float lo, float hi) {
    unsigned long long r; asm("mov.b64 %0, {%1, %2};" : "=l"(r) : "f"(lo), "f"(hi)); return r;
}
__device__ __forceinline__ void upk2(unsigned long long v, float& lo, float& hi) {
    asm("mov.b64 {%0, %1}, %2;" : "=f"(lo), "=f"(hi) : "l"(v));
}
__device__ __forceinline__ void fma2_(unsigned long long& acc, unsigned long long a, unsigned long long b) {
    asm("fma.rn.f32x2 %0, %1, %2, %0;" : "+l"(acc) : "l"(a), "l"(b));
}
__device__ __forceinline__ unsigned long long add2_(unsigned long long a, unsigned long long b) {
    unsigned long long r; asm("add.rn.f32x2 %0, %1, %2;" : "=l"(r) : "l"(a), "l"(b)); return r;
}
// Split-phase named barrier 1, expected count 512 = 256 threads x 2 arrivals
// (one bar.arrive + one bar.sync per thread per phase).
__device__ __forceinline__ void bar1_arrive_() {
    asm volatile("bar.arrive 1, 512;" ::: "memory");
}
__device__ __forceinline__ void bar1_sync_() {
    asm volatile("bar.sync 1, 512;" ::: "memory");
}

// One CTA per batch, 256 threads (8 warps) — the exact R3 configuration
// (measured optimum of this family: 634 cyc/step; all structural variants
// R4-R11 regressed), with ONE change: the per-step __syncthreads is replaced
// by a split-phase named barrier. After STS of the new forward vector each
// thread does bar.arrive and then runs the NEXT step's independent work
// (obs[t+4] LDG issue + next-step ex2 observation factors) in the overlap
// window while laggard warps finish; bar.sync at the top of the next
// iteration releases once all 512 arrivals (arrive+sync per thread) land.
// This removes the off-chain work from the post-release serial region and
// converts barrier arrival spread into useful overlap. STS -> bar.arrive,
// bar.sync -> LDS is the canonical PTX named-barrier producer pattern.
// Everything else identical to R3: cp = tid>>2 -> column pair (j0, j0+1),
// ich = tid&3 -> 32-wide from-chunk, E in registers i-pair packed, 16
// LDS.64 + 32 fma.rn.f32x2 + 2 shfl per thread/step, linear-domain forward
// vector in double-buffered padded smem, exact power-of-2 renorm every 8
// steps (REDUX publish t%8==0, fold t%8==1), 4-deep obs prefetch ring.
__global__ __launch_bounds__(256, 1)
void crf_fwd_kernel(const float* __restrict__ obs,
                    const float* __restrict__ logA,
                    float* __restrict__ out,
                    int T)
{
    constexpr int S  = 128;
    constexpr int CH = 34;     // chunk stride (floats): 8B-aligned, bank-skewed
    __shared__ __align__(16) float v_sm[2][4 * CH];
    __shared__ float wm[8];
    __shared__ float wsum[4];

    const int tid  = threadIdx.x;
    const int b    = blockIdx.x;
    const int cp   = tid >> 2;
    const int ich  = tid & 3;
    const int j0   = cp * 2;
    const int warp = tid >> 5;
    const int wslot = ((j0 >> 5) * CH) + (j0 & 31);

    const float* ob = obs + (size_t)b * (size_t)T * S + j0;

    // A0[k] = {E[i0+2k][j0],   E[i0+2k+1][j0]}
    // A1[k] = {E[i0+2k][j0+1], E[i0+2k+1][j0+1]},  i0 = 32*ich
    unsigned long long A0[16], A1[16];
#pragma unroll
    for (int k = 0; k < 16; ++k) {
        const int i0 = ich * 32 + 2 * k;
        const float2 ea = *reinterpret_cast<const float2*>(logA + (size_t)i0 * S + j0);
        const float2 eb = *reinterpret_cast<const float2*>(logA + (size_t)(i0 + 1) * S + j0);
        A0[k] = pk2(ex2f_(ea.x * LOG2E_F), ex2f_(eb.x * LOG2E_F));
        A1[k] = pk2(ex2f_(ea.y * LOG2E_F), ex2f_(eb.y * LOG2E_F));
    }

    // ---- t = 0 (t%8==0): u = exp(obs[0]) raw; publish block max ----
    const float2 o0 = *reinterpret_cast<const float2*>(ob);
    const float u0 = ex2f_(o0.x * LOG2E_F);
    const float u1 = ex2f_(o0.y * LOG2E_F);
    {
        const int im = __reduce_max_sync(0xffffffffu, __float_as_int(fmaxf(u0, u1)));
        if ((tid & 31) == 0) wm[warp] = __int_as_float(im);
        if (ich == 0) {
            float2 w; w.x = u0; w.y = u1;
            *reinterpret_cast<float2*>(&v_sm[0][wslot]) = w;
        }
    }

    // 4-deep obs prefetch ring: oR[t & 3] holds obs[t].
    float2 oR[4];
#pragma unroll
    for (int k = 1; k <= 4; ++k)
        oR[k & 3] = (k < T) ? __ldcs(reinterpret_cast<const float2*>(ob + (size_t)k * S)) : o0;

    int L = 0;                 // exact accumulated log2 scale (uniform across block)

    // Enter phase 1: initial STS/wm published above.
    bar1_arrive_();
    // Overlap window before the first sync: observation factors for t = 1.
    float pn0 = ex2f_(oR[1].x * LOG2E_F);
    float pn1 = ex2f_(oR[1].y * LOG2E_F);

    // ---- scan t = 1 .. T-1: sync at top, arrive after STS, tail overlapped ----
#pragma unroll 4
    for (int t = 1; t < T; ++t) {
        const int cb = (t - 1) & 1, nb = t & 1;

        // observation factors for THIS step (computed in last overlap window)
        const float p0 = pn0;
        const float p1 = pn1;

        bar1_sync_();   // release: all STS (v, wm) of the previous phase visible

        // fold previous publish's exact 2^-e every 8th step
        float sc = 1.0f;
        const bool fold = (t & 7) == 1;
        if (fold) {
            const float m = fmaxf(fmaxf(fmaxf(wm[0], wm[1]), fmaxf(wm[2], wm[3])),
                                  fmaxf(fmaxf(wm[4], wm[5]), fmaxf(wm[6], wm[7])));
            const int e = ((__float_as_int(m) >> 23) & 0xFF) - 127;
            L += e;
            sc = __int_as_float((127 - e) << 23);   // exact 2^-e
        }

        // matvec over this thread's 32-i chunk: 16 LDS.64, 4 fma2 chains
        const unsigned long long* V =
            reinterpret_cast<const unsigned long long*>(&v_sm[cb][ich * CH]);
        unsigned long long c0a = 0ull, c0b = 0ull, c1a = 0ull, c1b = 0ull;
#pragma unroll
        for (int k = 0; k < 8; ++k) {
            const unsigned long long va = V[2 * k], vb = V[2 * k + 1];
            fma2_(c0a, va, A0[2 * k]);
            fma2_(c1a, va, A1[2 * k]);
            fma2_(c0b, vb, A0[2 * k + 1]);
            fma2_(c1b, vb, A1[2 * k + 1]);
        }
        float x0, y0, x1, y1;
        upk2(add2_(c0a, c0b), x0, y0);
        upk2(add2_(c1a, c1b), x1, y1);
        float acc0 = x0 + y0;
        float acc1 = x1 + y1;
        // butterfly across the 4 i-chunks (lane^1, lane^2 flip only ich)
        acc0 += __shfl_xor_sync(0xffffffffu, acc0, 1);
        acc1 += __shfl_xor_sync(0xffffffffu, acc1, 1);
        acc0 += __shfl_xor_sync(0xffffffffu, acc0, 2);
        acc1 += __shfl_xor_sync(0xffffffffu, acc1, 2);

        const float un0 = fold ? acc0 * (p0 * sc) : acc0 * p0;
        const float un1 = fold ? acc1 * (p1 * sc) : acc1 * p1;

        if (ich == 0) {
            float2 w; w.x = un0; w.y = un1;
            *reinterpret_cast<float2*>(&v_sm[nb][wslot]) = w;
        }
        // publish block max every 8th step (must precede the arrive)
        if ((t & 7) == 0) {
            const int im = __reduce_max_sync(0xffffffffu, __float_as_int(fmaxf(un0, un1)));
            if ((tid & 31) == 0) wm[warp] = __int_as_float(im);
        }

        bar1_arrive_();   // phase t published; laggards may still be working

        // -------- overlap window: next step's independent work --------
        if (t + 4 < T)
            oR[t & 3] = __ldcs(reinterpret_cast<const float2*>(ob + (size_t)(t + 4) * S));
        const float2 on = oR[(t + 1) & 3];
        pn0 = ex2f_(on.x * LOG2E_F);
        pn1 = ex2f_(on.y * LOG2E_F);
    }
    bar1_sync_();   // complete the final phase

    // ---- finalize: out[b] = -ln2 * (log2(sum_j v_j) + L) ----
    const int fb = (T - 1) & 1;
    float vv = 0.f;
    if (tid < 128) vv = v_sm[fb][((tid >> 5) * CH) + (tid & 31)];
#pragma unroll
    for (int o = 16; o; o >>= 1) vv += __shfl_xor_sync(0xffffffffu, vv, o);
    if (tid < 128 && (tid & 31) == 0) wsum[tid >> 5] = vv;
    __syncthreads();
    if (tid == 0) {
        const float s = (wsum[0] + wsum[1]) + (wsum[2] + wsum[3]);
        out[b] = -LN2_F * (lg2f_(s) + (float)L);
    }
}

extern "C" void kernel_launch(void* const* d_in, const int* in_sizes, int n_in,
                              void* d_out, int out_size)
{
    const float* obs  = (const float*)d_in[0];   // [B, T, S] f32
    const float* logA = (const float*)d_in[1];   // [S, S]   f32
    float* out = (float*)d_out;                  // [B]      f32

    const int B = out_size;
    const int S = 128;
    const int T = in_sizes[0] / (B * S);

    crf_fwd_kernel<<<B, 256>>>(obs, logA, out, T);
}